// round 3
// baseline (speedup 1.0000x reference)
#include <cuda_runtime.h>
#include <cuda_bf16.h>
#include <cstdint>

// Problem constants
#define Bb   4
#define Nn   1024
#define Hh   16
#define Dd   72
#define HIDc 1152
#define ATTc 1152          // H*D
#define BHc  (Bb*Hh)       // 64
#define Mrows (Bb*Nn)      // 4096

// Scratch (static device globals; allocation inside kernel_launch is forbidden)
__device__ float g_q[(size_t)BHc * Nn * Dd];       // [b,h,n,d], pre-scaled by D^-0.5
__device__ float g_k[(size_t)BHc * Nn * Dd];       // [b,h,n,d]
__device__ float g_v[(size_t)BHc * Nn * Dd];       // [b,h,n,d]
__device__ float g_s[(size_t)BHc * Nn * Nn];       // [bh, i, j] logits -> probs
__device__ float g_att[(size_t)Bb * Nn * ATTc];    // [b, n, h*D]

// ---------------------------------------------------------------------------
// Generic 128x128 register-blocked SGEMM core.
//   C[128x128] tile at (m0, n0); A is row-major [*, lda]; if BT==false, B is
//   row-major [K, ldb] (element B[k][n]); if BT==true, B is row-major [N, ldb]
//   and we compute A @ B^T (element B[n][k]).
//   256 threads, per-thread 8x8 accumulator, BK in {8,16}, double-buffered.
// ---------------------------------------------------------------------------
template <int BK, bool BT>
__device__ __forceinline__ void gemm_core(
    const float* __restrict__ A, const float* __restrict__ Bm,
    int lda, int ldb, int Kdim, int m0, int n0,
    float (&acc)[8][8])
{
    constexpr int AV = BK / 8;              // float4 loads per thread per operand
    __shared__ float As[2][BK][128];
    __shared__ float Bs[2][BK][128];

    const int tid = threadIdx.x;
    const int ty = tid >> 4;                // 0..15 (m)
    const int tx = tid & 15;                // 0..15 (n)

    float4 pa[AV], pb[AV];

    auto ldgA = [&](int k0, int u) -> float4 {
        int idx = tid + u * 256;
        int r = idx / (BK / 4);
        int c = idx % (BK / 4);
        return *reinterpret_cast<const float4*>(
            &A[(size_t)(m0 + r) * lda + k0 + c * 4]);
    };
    auto stsA = [&](int buf, int u, float4 v) {
        int idx = tid + u * 256;
        int r = idx / (BK / 4);
        int c = idx % (BK / 4);
        As[buf][c * 4 + 0][r] = v.x;
        As[buf][c * 4 + 1][r] = v.y;
        As[buf][c * 4 + 2][r] = v.z;
        As[buf][c * 4 + 3][r] = v.w;
    };
    auto ldgB = [&](int k0, int u) -> float4 {
        int idx = tid + u * 256;
        if constexpr (BT) {
            int r = idx / (BK / 4);         // n row
            int c = idx % (BK / 4);
            return *reinterpret_cast<const float4*>(
                &Bm[(size_t)(n0 + r) * ldb + k0 + c * 4]);
        } else {
            int r = idx >> 5;               // k row
            int c = idx & 31;
            return *reinterpret_cast<const float4*>(
                &Bm[(size_t)(k0 + r) * ldb + n0 + c * 4]);
        }
    };
    auto stsB = [&](int buf, int u, float4 v) {
        int idx = tid + u * 256;
        if constexpr (BT) {
            int r = idx / (BK / 4);
            int c = idx % (BK / 4);
            Bs[buf][c * 4 + 0][r] = v.x;
            Bs[buf][c * 4 + 1][r] = v.y;
            Bs[buf][c * 4 + 2][r] = v.z;
            Bs[buf][c * 4 + 3][r] = v.w;
        } else {
            int r = idx >> 5;
            int c = idx & 31;
            *reinterpret_cast<float4*>(&Bs[buf][r][c * 4]) = v;
        }
    };

    const int nkt = Kdim / BK;

    #pragma unroll
    for (int u = 0; u < AV; u++) { pa[u] = ldgA(0, u); pb[u] = ldgB(0, u); }
    #pragma unroll
    for (int u = 0; u < AV; u++) { stsA(0, u, pa[u]); stsB(0, u, pb[u]); }
    __syncthreads();

    for (int kt = 0; kt < nkt; kt++) {
        const int buf = kt & 1;
        const bool more = (kt + 1 < nkt);
        if (more) {
            #pragma unroll
            for (int u = 0; u < AV; u++) {
                pa[u] = ldgA((kt + 1) * BK, u);
                pb[u] = ldgB((kt + 1) * BK, u);
            }
        }
        #pragma unroll
        for (int k = 0; k < BK; k++) {
            float4 a0 = *reinterpret_cast<const float4*>(&As[buf][k][ty * 8]);
            float4 a1 = *reinterpret_cast<const float4*>(&As[buf][k][ty * 8 + 4]);
            float4 b0 = *reinterpret_cast<const float4*>(&Bs[buf][k][tx * 8]);
            float4 b1 = *reinterpret_cast<const float4*>(&Bs[buf][k][tx * 8 + 4]);
            float av[8] = {a0.x, a0.y, a0.z, a0.w, a1.x, a1.y, a1.z, a1.w};
            float bv[8] = {b0.x, b0.y, b0.z, b0.w, b1.x, b1.y, b1.z, b1.w};
            #pragma unroll
            for (int i = 0; i < 8; i++)
                #pragma unroll
                for (int j = 0; j < 8; j++)
                    acc[i][j] += av[i] * bv[j];
        }
        if (more) {
            #pragma unroll
            for (int u = 0; u < AV; u++) { stsA(buf ^ 1, u, pa[u]); stsB(buf ^ 1, u, pb[u]); }
            __syncthreads();
        }
    }
}

// ---------------------------------------------------------------------------
// Kernel 1: qkv = x @ w_qkv + b_qkv, scattered to g_q/g_k/g_v in [B,H,N,D].
// Q is pre-scaled by D^-0.5. grid (3456/128=27, 4096/128=32), 256 threads.
// N-tile never crosses a q/k/v boundary (1152 % 128 == 0).
// ---------------------------------------------------------------------------
__global__ __launch_bounds__(256)
void qkv_kernel(const float* __restrict__ x, const float* __restrict__ w,
                const float* __restrict__ bias)
{
    const int n0 = blockIdx.x * 128;
    const int m0 = blockIdx.y * 128;
    float acc[8][8] = {};
    gemm_core<16, false>(x, w, HIDc, 3 * ATTc, HIDc, m0, n0, acc);

    const int ty = threadIdx.x >> 4, tx = threadIdx.x & 15;
    const int which = n0 / ATTc;                       // 0=q, 1=k, 2=v
    float* dst = (which == 0) ? g_q : (which == 1) ? g_k : g_v;
    const float sc = (which == 0) ? 0.11785113019775793f : 1.0f;  // 72^-0.5

    #pragma unroll
    for (int i = 0; i < 8; i++) {
        int m = m0 + ty * 8 + i;
        int bi = m >> 10;
        int r  = m & 1023;
        #pragma unroll
        for (int j = 0; j < 8; j++) {
            int n = n0 + tx * 8 + j;
            int c = n - which * ATTc;
            int h = c / Dd;
            int d = c - h * Dd;
            float v = (acc[i][j] + bias[n]) * sc;
            dst[(size_t)((bi * Hh + h) * Nn + r) * Dd + d] = v;
        }
    }
}

// ---------------------------------------------------------------------------
// Kernel 2a: S[bh] = Q[bh] @ K[bh]^T  (scale already folded into Q).
// grid (1024/128=8, 8, 64), 256 threads, K-dim = 72, BK=8.
// ---------------------------------------------------------------------------
__global__ __launch_bounds__(256)
void qk_kernel()
{
    const int bh = blockIdx.z;
    const int n0 = blockIdx.x * 128;
    const int m0 = blockIdx.y * 128;
    const float* Q  = g_q + (size_t)bh * Nn * Dd;
    const float* Kp = g_k + (size_t)bh * Nn * Dd;

    float acc[8][8] = {};
    gemm_core<8, true>(Q, Kp, Dd, Dd, Dd, m0, n0, acc);

    const int ty = threadIdx.x >> 4, tx = threadIdx.x & 15;
    float* Sp = g_s + (size_t)bh * Nn * Nn;
    #pragma unroll
    for (int i = 0; i < 8; i++) {
        int row = m0 + ty * 8 + i;
        float4 o0 = make_float4(acc[i][0], acc[i][1], acc[i][2], acc[i][3]);
        float4 o1 = make_float4(acc[i][4], acc[i][5], acc[i][6], acc[i][7]);
        float* p = &Sp[(size_t)row * Nn + n0 + tx * 8];
        *reinterpret_cast<float4*>(p)     = o0;
        *reinterpret_cast<float4*>(p + 4) = o1;
    }
}

// ---------------------------------------------------------------------------
// Kernel 2b: in-place row softmax over g_s. One block (256 thr) per 1024-row.
// grid = 64*1024 = 65536.
// ---------------------------------------------------------------------------
__global__ __launch_bounds__(256)
void softmax_kernel()
{
    __shared__ float sred[8];
    const size_t row = blockIdx.x;
    float* p = g_s + row * Nn;
    const int t = threadIdx.x;

    float4 v = reinterpret_cast<float4*>(p)[t];

    float mx = fmaxf(fmaxf(v.x, v.y), fmaxf(v.z, v.w));
    #pragma unroll
    for (int o = 16; o; o >>= 1) mx = fmaxf(mx, __shfl_xor_sync(0xffffffffu, mx, o));
    if ((t & 31) == 0) sred[t >> 5] = mx;
    __syncthreads();
    mx = sred[t & 7];
    #pragma unroll
    for (int o = 4; o; o >>= 1) mx = fmaxf(mx, __shfl_xor_sync(0xffffffffu, mx, o));

    v.x = __expf(v.x - mx); v.y = __expf(v.y - mx);
    v.z = __expf(v.z - mx); v.w = __expf(v.w - mx);

    float sm = v.x + v.y + v.z + v.w;
    #pragma unroll
    for (int o = 16; o; o >>= 1) sm += __shfl_xor_sync(0xffffffffu, sm, o);
    __syncthreads();                       // protect sred reuse
    if ((t & 31) == 0) sred[t >> 5] = sm;
    __syncthreads();
    sm = sred[t & 7];
    #pragma unroll
    for (int o = 4; o; o >>= 1) sm += __shfl_xor_sync(0xffffffffu, sm, o);

    float inv = 1.0f / sm;
    v.x *= inv; v.y *= inv; v.z *= inv; v.w *= inv;
    reinterpret_cast<float4*>(p)[t] = v;
}

// ---------------------------------------------------------------------------
// Kernel 2c: O[bh] = P[bh] @ V[bh]  (1024x72x1024), written to g_att [B,N,H*D].
// Block tile 128x72, BK=16, 256 threads as 32(ty: 4 rows) x 8(tx: 9 cols).
// grid (8, 64).
// ---------------------------------------------------------------------------
__global__ __launch_bounds__(256)
void pv_kernel()
{
    __shared__ float As[2][16][128];
    __shared__ float Vs[2][16][80];        // 72 cols padded to 80

    const int bh = blockIdx.y;
    const int m0 = blockIdx.x * 128;
    const float* P = g_s + (size_t)bh * Nn * Nn;
    const float* V = g_v + (size_t)bh * Nn * Dd;

    const int tid = threadIdx.x;
    const int ty = tid >> 3;               // 0..31 -> 4 rows each
    const int tx = tid & 7;                // 0..7  -> 9 cols each
    const bool hasV2 = (tid < 32);         // V tile = 288 float4 = 256 + 32

    float acc[4][9] = {};

    auto ldgA = [&](int k0, int u) -> float4 {
        int idx = tid + u * 256;
        int r = idx >> 2, c = idx & 3;
        return *reinterpret_cast<const float4*>(&P[(size_t)(m0 + r) * Nn + k0 + c * 4]);
    };
    auto stsA = [&](int buf, int u, float4 v) {
        int idx = tid + u * 256;
        int r = idx >> 2, c = idx & 3;
        As[buf][c * 4 + 0][r] = v.x;
        As[buf][c * 4 + 1][r] = v.y;
        As[buf][c * 4 + 2][r] = v.z;
        As[buf][c * 4 + 3][r] = v.w;
    };
    auto ldgV = [&](int k0, int u) -> float4 {
        int idx = tid + u * 256;           // caller guarantees idx < 288
        int r = idx / 18, c = idx % 18;
        return *reinterpret_cast<const float4*>(&V[(size_t)(k0 + r) * Dd + c * 4]);
    };
    auto stsV = [&](int buf, int u, float4 v) {
        int idx = tid + u * 256;
        int r = idx / 18, c = idx % 18;
        *reinterpret_cast<float4*>(&Vs[buf][r][c * 4]) = v;
    };

    const int nkt = Nn / 16;               // 64

    float4 pa0 = ldgA(0, 0), pa1 = ldgA(0, 1);
    float4 pv0 = ldgV(0, 0);
    float4 pv1 = hasV2 ? ldgV(0, 1) : make_float4(0, 0, 0, 0);
    stsA(0, 0, pa0); stsA(0, 1, pa1);
    stsV(0, 0, pv0);
    if (hasV2) stsV(0, 1, pv1);
    __syncthreads();

    for (int kt = 0; kt < nkt; kt++) {
        const int buf = kt & 1;
        const bool more = (kt + 1 < nkt);
        if (more) {
            int k0 = (kt + 1) * 16;
            pa0 = ldgA(k0, 0); pa1 = ldgA(k0, 1);
            pv0 = ldgV(k0, 0);
            if (hasV2) pv1 = ldgV(k0, 1);
        }
        #pragma unroll
        for (int k = 0; k < 16; k++) {
            float4 a = *reinterpret_cast<const float4*>(&As[buf][k][ty * 4]);
            float av[4] = {a.x, a.y, a.z, a.w};
            float bv[9];
            #pragma unroll
            for (int j = 0; j < 9; j++) bv[j] = Vs[buf][k][tx * 9 + j];
            #pragma unroll
            for (int r = 0; r < 4; r++)
                #pragma unroll
                for (int j = 0; j < 9; j++)
                    acc[r][j] += av[r] * bv[j];
        }
        if (more) {
            stsA(buf ^ 1, 0, pa0); stsA(buf ^ 1, 1, pa1);
            stsV(buf ^ 1, 0, pv0);
            if (hasV2) stsV(buf ^ 1, 1, pv1);
            __syncthreads();
        }
    }

    const int b = bh >> 4, h = bh & 15;
    #pragma unroll
    for (int r = 0; r < 4; r++) {
        int m = m0 + ty * 4 + r;
        float* orow = g_att + (size_t)(b * Nn + m) * ATTc + h * Dd + tx * 9;
        #pragma unroll
        for (int j = 0; j < 9; j++) orow[j] = acc[r][j];
    }
}

// ---------------------------------------------------------------------------
// Kernel 3: out = g_att @ w_out + b_out. grid (1152/128=9, 4096/128=32).
// ---------------------------------------------------------------------------
__global__ __launch_bounds__(256)
void out_kernel(const float* __restrict__ w, const float* __restrict__ bias,
                float* __restrict__ out)
{
    const int n0 = blockIdx.x * 128;
    const int m0 = blockIdx.y * 128;
    float acc[8][8] = {};
    gemm_core<16, false>(g_att, w, ATTc, HIDc, ATTc, m0, n0, acc);

    const int ty = threadIdx.x >> 4, tx = threadIdx.x & 15;
    #pragma unroll
    for (int i = 0; i < 8; i++) {
        int m = m0 + ty * 8 + i;
        int nb = n0 + tx * 8;
        float4 o0 = make_float4(acc[i][0] + bias[nb + 0], acc[i][1] + bias[nb + 1],
                                acc[i][2] + bias[nb + 2], acc[i][3] + bias[nb + 3]);
        float4 o1 = make_float4(acc[i][4] + bias[nb + 4], acc[i][5] + bias[nb + 5],
                                acc[i][6] + bias[nb + 6], acc[i][7] + bias[nb + 7]);
        float* p = &out[(size_t)m * HIDc + nb];
        *reinterpret_cast<float4*>(p)     = o0;
        *reinterpret_cast<float4*>(p + 4) = o1;
    }
}

// ---------------------------------------------------------------------------
// Entry point. Inputs (metadata order): x, w_qkv, b_qkv, w_out, b_out.
// Output: fp32 [B, N, HID]. All launches are plain kernels -> graph-capturable.
// ---------------------------------------------------------------------------
extern "C" void kernel_launch(void* const* d_in, const int* in_sizes, int n_in,
                              void* d_out, int out_size)
{
    const float* x     = (const float*)d_in[0];
    const float* w_qkv = (const float*)d_in[1];
    const float* b_qkv = (const float*)d_in[2];
    const float* w_out = (const float*)d_in[3];
    const float* b_out = (const float*)d_in[4];
    float* out = (float*)d_out;

    qkv_kernel<<<dim3(27, 32), 256>>>(x, w_qkv, b_qkv);
    qk_kernel<<<dim3(8, 8, 64), 256>>>();
    softmax_kernel<<<65536, 256>>>();
    pv_kernel<<<dim3(8, 64), 256>>>();
    out_kernel<<<dim3(9, 32), 256>>>(w_out, b_out, out);
}

// round 4
// speedup vs baseline: 1.0031x; 1.0031x over previous
#include <cuda_runtime.h>
#include <cuda_bf16.h>
#include <cstdint>

// Problem constants
#define Bb   4
#define Nn   1024
#define Hh   16
#define Dd   72
#define HIDc 1152
#define ATTc 1152          // H*D
#define BHc  (Bb*Hh)       // 64
#define Mrows (Bb*Nn)      // 4096

// Scratch (static device globals; allocation inside kernel_launch is forbidden)
__device__ float g_q[(size_t)BHc * Nn * Dd];       // [b,h,n,d], pre-scaled by D^-0.5
__device__ float g_k[(size_t)BHc * Nn * Dd];       // [b,h,n,d]
__device__ float g_v[(size_t)BHc * Nn * Dd];       // [b,h,n,d]
__device__ float g_s[(size_t)BHc * Nn * Nn];       // [bh, i, j] logits -> probs
__device__ float g_att[(size_t)Bb * Nn * ATTc];    // [b, n, h*D]

// ---------------------------------------------------------------------------
// Generic 128x128 register-blocked SGEMM core.
//   C[128x128] tile at (m0, n0); A is row-major [*, lda]; if BT==false, B is
//   row-major [K, ldb] (element B[k][n]); if BT==true, B is row-major [N, ldb]
//   and we compute A @ B^T (element B[n][k]).
//   256 threads, per-thread 8x8 accumulator, BK in {8,16}, double-buffered.
// ---------------------------------------------------------------------------
template <int BK, bool BT>
__device__ __forceinline__ void gemm_core(
    const float* __restrict__ A, const float* __restrict__ Bm,
    int lda, int ldb, int Kdim, int m0, int n0,
    float (&acc)[8][8])
{
    constexpr int AV = BK / 8;              // float4 loads per thread per operand
    __shared__ float As[2][BK][128];
    __shared__ float Bs[2][BK][128];

    const int tid = threadIdx.x;
    const int ty = tid >> 4;                // 0..15 (m)
    const int tx = tid & 15;                // 0..15 (n)

    float4 pa[AV], pb[AV];

    auto ldgA = [&](int k0, int u) -> float4 {
        int idx = tid + u * 256;
        int r = idx / (BK / 4);
        int c = idx % (BK / 4);
        return *reinterpret_cast<const float4*>(
            &A[(size_t)(m0 + r) * lda + k0 + c * 4]);
    };
    auto stsA = [&](int buf, int u, float4 v) {
        int idx = tid + u * 256;
        int r = idx / (BK / 4);
        int c = idx % (BK / 4);
        As[buf][c * 4 + 0][r] = v.x;
        As[buf][c * 4 + 1][r] = v.y;
        As[buf][c * 4 + 2][r] = v.z;
        As[buf][c * 4 + 3][r] = v.w;
    };
    auto ldgB = [&](int k0, int u) -> float4 {
        int idx = tid + u * 256;
        if constexpr (BT) {
            int r = idx / (BK / 4);         // n row
            int c = idx % (BK / 4);
            return *reinterpret_cast<const float4*>(
                &Bm[(size_t)(n0 + r) * ldb + k0 + c * 4]);
        } else {
            int r = idx >> 5;               // k row
            int c = idx & 31;
            return *reinterpret_cast<const float4*>(
                &Bm[(size_t)(k0 + r) * ldb + n0 + c * 4]);
        }
    };
    auto stsB = [&](int buf, int u, float4 v) {
        int idx = tid + u * 256;
        if constexpr (BT) {
            int r = idx / (BK / 4);
            int c = idx % (BK / 4);
            Bs[buf][c * 4 + 0][r] = v.x;
            Bs[buf][c * 4 + 1][r] = v.y;
            Bs[buf][c * 4 + 2][r] = v.z;
            Bs[buf][c * 4 + 3][r] = v.w;
        } else {
            int r = idx >> 5;
            int c = idx & 31;
            *reinterpret_cast<float4*>(&Bs[buf][r][c * 4]) = v;
        }
    };

    const int nkt = Kdim / BK;

    #pragma unroll
    for (int u = 0; u < AV; u++) { pa[u] = ldgA(0, u); pb[u] = ldgB(0, u); }
    #pragma unroll
    for (int u = 0; u < AV; u++) { stsA(0, u, pa[u]); stsB(0, u, pb[u]); }
    __syncthreads();

    for (int kt = 0; kt < nkt; kt++) {
        const int buf = kt & 1;
        const bool more = (kt + 1 < nkt);
        if (more) {
            #pragma unroll
            for (int u = 0; u < AV; u++) {
                pa[u] = ldgA((kt + 1) * BK, u);
                pb[u] = ldgB((kt + 1) * BK, u);
            }
        }
        #pragma unroll
        for (int k = 0; k < BK; k++) {
            float4 a0 = *reinterpret_cast<const float4*>(&As[buf][k][ty * 8]);
            float4 a1 = *reinterpret_cast<const float4*>(&As[buf][k][ty * 8 + 4]);
            float4 b0 = *reinterpret_cast<const float4*>(&Bs[buf][k][tx * 8]);
            float4 b1 = *reinterpret_cast<const float4*>(&Bs[buf][k][tx * 8 + 4]);
            float av[8] = {a0.x, a0.y, a0.z, a0.w, a1.x, a1.y, a1.z, a1.w};
            float bv[8] = {b0.x, b0.y, b0.z, b0.w, b1.x, b1.y, b1.z, b1.w};
            #pragma unroll
            for (int i = 0; i < 8; i++)
                #pragma unroll
                for (int j = 0; j < 8; j++)
                    acc[i][j] += av[i] * bv[j];
        }
        if (more) {
            #pragma unroll
            for (int u = 0; u < AV; u++) { stsA(buf ^ 1, u, pa[u]); stsB(buf ^ 1, u, pb[u]); }
            __syncthreads();
        }
    }
}

// ---------------------------------------------------------------------------
// Kernel 1: qkv = x @ w_qkv + b_qkv, scattered to g_q/g_k/g_v in [B,H,N,D].
// Q is pre-scaled by D^-0.5. grid (3456/128=27, 4096/128=32), 256 threads.
// N-tile never crosses a q/k/v boundary (1152 % 128 == 0).
// ---------------------------------------------------------------------------
__global__ __launch_bounds__(256)
void qkv_kernel(const float* __restrict__ x, const float* __restrict__ w,
                const float* __restrict__ bias)
{
    const int n0 = blockIdx.x * 128;
    const int m0 = blockIdx.y * 128;
    float acc[8][8] = {};
    gemm_core<16, false>(x, w, HIDc, 3 * ATTc, HIDc, m0, n0, acc);

    const int ty = threadIdx.x >> 4, tx = threadIdx.x & 15;
    const int which = n0 / ATTc;                       // 0=q, 1=k, 2=v
    float* dst = (which == 0) ? g_q : (which == 1) ? g_k : g_v;
    const float sc = (which == 0) ? 0.11785113019775793f : 1.0f;  // 72^-0.5

    #pragma unroll
    for (int i = 0; i < 8; i++) {
        int m = m0 + ty * 8 + i;
        int bi = m >> 10;
        int r  = m & 1023;
        #pragma unroll
        for (int j = 0; j < 8; j++) {
            int n = n0 + tx * 8 + j;
            int c = n - which * ATTc;
            int h = c / Dd;
            int d = c - h * Dd;
            float v = (acc[i][j] + bias[n]) * sc;
            dst[(size_t)((bi * Hh + h) * Nn + r) * Dd + d] = v;
        }
    }
}

// ---------------------------------------------------------------------------
// Kernel 2a: S[bh] = Q[bh] @ K[bh]^T  (scale already folded into Q).
// grid (1024/128=8, 8, 64), 256 threads, K-dim = 72, BK=8.
// ---------------------------------------------------------------------------
__global__ __launch_bounds__(256)
void qk_kernel()
{
    const int bh = blockIdx.z;
    const int n0 = blockIdx.x * 128;
    const int m0 = blockIdx.y * 128;
    const float* Q  = g_q + (size_t)bh * Nn * Dd;
    const float* Kp = g_k + (size_t)bh * Nn * Dd;

    float acc[8][8] = {};
    gemm_core<8, true>(Q, Kp, Dd, Dd, Dd, m0, n0, acc);

    const int ty = threadIdx.x >> 4, tx = threadIdx.x & 15;
    float* Sp = g_s + (size_t)bh * Nn * Nn;
    #pragma unroll
    for (int i = 0; i < 8; i++) {
        int row = m0 + ty * 8 + i;
        float4 o0 = make_float4(acc[i][0], acc[i][1], acc[i][2], acc[i][3]);
        float4 o1 = make_float4(acc[i][4], acc[i][5], acc[i][6], acc[i][7]);
        float* p = &Sp[(size_t)row * Nn + n0 + tx * 8];
        *reinterpret_cast<float4*>(p)     = o0;
        *reinterpret_cast<float4*>(p + 4) = o1;
    }
}

// ---------------------------------------------------------------------------
// Kernel 2b: in-place row softmax over g_s. One block (256 thr) per 1024-row.
// grid = 64*1024 = 65536.
// ---------------------------------------------------------------------------
__global__ __launch_bounds__(256)
void softmax_kernel()
{
    __shared__ float sred[8];
    const size_t row = blockIdx.x;
    float* p = g_s + row * Nn;
    const int t = threadIdx.x;

    float4 v = reinterpret_cast<float4*>(p)[t];

    float mx = fmaxf(fmaxf(v.x, v.y), fmaxf(v.z, v.w));
    #pragma unroll
    for (int o = 16; o; o >>= 1) mx = fmaxf(mx, __shfl_xor_sync(0xffffffffu, mx, o));
    if ((t & 31) == 0) sred[t >> 5] = mx;
    __syncthreads();
    mx = sred[t & 7];
    #pragma unroll
    for (int o = 4; o; o >>= 1) mx = fmaxf(mx, __shfl_xor_sync(0xffffffffu, mx, o));

    v.x = __expf(v.x - mx); v.y = __expf(v.y - mx);
    v.z = __expf(v.z - mx); v.w = __expf(v.w - mx);

    float sm = v.x + v.y + v.z + v.w;
    #pragma unroll
    for (int o = 16; o; o >>= 1) sm += __shfl_xor_sync(0xffffffffu, sm, o);
    __syncthreads();                       // protect sred reuse
    if ((t & 31) == 0) sred[t >> 5] = sm;
    __syncthreads();
    sm = sred[t & 7];
    #pragma unroll
    for (int o = 4; o; o >>= 1) sm += __shfl_xor_sync(0xffffffffu, sm, o);

    float inv = 1.0f / sm;
    v.x *= inv; v.y *= inv; v.z *= inv; v.w *= inv;
    reinterpret_cast<float4*>(p)[t] = v;
}

// ---------------------------------------------------------------------------
// Kernel 2c: O[bh] = P[bh] @ V[bh]  (1024x72x1024), written to g_att [B,N,H*D].
// Block tile 128x72, BK=16, 256 threads as 32(ty: 4 rows) x 8(tx: 9 cols).
// grid (8, 64).
// ---------------------------------------------------------------------------
__global__ __launch_bounds__(256)
void pv_kernel()
{
    __shared__ float As[2][16][128];
    __shared__ float Vs[2][16][80];        // 72 cols padded to 80

    const int bh = blockIdx.y;
    const int m0 = blockIdx.x * 128;
    const float* P = g_s + (size_t)bh * Nn * Nn;
    const float* V = g_v + (size_t)bh * Nn * Dd;

    const int tid = threadIdx.x;
    const int ty = tid >> 3;               // 0..31 -> 4 rows each
    const int tx = tid & 7;                // 0..7  -> 9 cols each
    const bool hasV2 = (tid < 32);         // V tile = 288 float4 = 256 + 32

    float acc[4][9] = {};

    auto ldgA = [&](int k0, int u) -> float4 {
        int idx = tid + u * 256;
        int r = idx >> 2, c = idx & 3;
        return *reinterpret_cast<const float4*>(&P[(size_t)(m0 + r) * Nn + k0 + c * 4]);
    };
    auto stsA = [&](int buf, int u, float4 v) {
        int idx = tid + u * 256;
        int r = idx >> 2, c = idx & 3;
        As[buf][c * 4 + 0][r] = v.x;
        As[buf][c * 4 + 1][r] = v.y;
        As[buf][c * 4 + 2][r] = v.z;
        As[buf][c * 4 + 3][r] = v.w;
    };
    auto ldgV = [&](int k0, int u) -> float4 {
        int idx = tid + u * 256;           // caller guarantees idx < 288
        int r = idx / 18, c = idx % 18;
        return *reinterpret_cast<const float4*>(&V[(size_t)(k0 + r) * Dd + c * 4]);
    };
    auto stsV = [&](int buf, int u, float4 v) {
        int idx = tid + u * 256;
        int r = idx / 18, c = idx % 18;
        *reinterpret_cast<float4*>(&Vs[buf][r][c * 4]) = v;
    };

    const int nkt = Nn / 16;               // 64

    float4 pa0 = ldgA(0, 0), pa1 = ldgA(0, 1);
    float4 pv0 = ldgV(0, 0);
    float4 pv1 = hasV2 ? ldgV(0, 1) : make_float4(0, 0, 0, 0);
    stsA(0, 0, pa0); stsA(0, 1, pa1);
    stsV(0, 0, pv0);
    if (hasV2) stsV(0, 1, pv1);
    __syncthreads();

    for (int kt = 0; kt < nkt; kt++) {
        const int buf = kt & 1;
        const bool more = (kt + 1 < nkt);
        if (more) {
            int k0 = (kt + 1) * 16;
            pa0 = ldgA(k0, 0); pa1 = ldgA(k0, 1);
            pv0 = ldgV(k0, 0);
            if (hasV2) pv1 = ldgV(k0, 1);
        }
        #pragma unroll
        for (int k = 0; k < 16; k++) {
            float4 a = *reinterpret_cast<const float4*>(&As[buf][k][ty * 4]);
            float av[4] = {a.x, a.y, a.z, a.w};
            float bv[9];
            #pragma unroll
            for (int j = 0; j < 9; j++) bv[j] = Vs[buf][k][tx * 9 + j];
            #pragma unroll
            for (int r = 0; r < 4; r++)
                #pragma unroll
                for (int j = 0; j < 9; j++)
                    acc[r][j] += av[r] * bv[j];
        }
        if (more) {
            stsA(buf ^ 1, 0, pa0); stsA(buf ^ 1, 1, pa1);
            stsV(buf ^ 1, 0, pv0);
            if (hasV2) stsV(buf ^ 1, 1, pv1);
            __syncthreads();
        }
    }

    const int b = bh >> 4, h = bh & 15;
    #pragma unroll
    for (int r = 0; r < 4; r++) {
        int m = m0 + ty * 4 + r;
        float* orow = g_att + (size_t)(b * Nn + m) * ATTc + h * Dd + tx * 9;
        #pragma unroll
        for (int j = 0; j < 9; j++) orow[j] = acc[r][j];
    }
}

// ---------------------------------------------------------------------------
// Kernel 3: out = g_att @ w_out + b_out. grid (1152/128=9, 4096/128=32).
// ---------------------------------------------------------------------------
__global__ __launch_bounds__(256)
void out_kernel(const float* __restrict__ w, const float* __restrict__ bias,
                float* __restrict__ out)
{
    const int n0 = blockIdx.x * 128;
    const int m0 = blockIdx.y * 128;
    float acc[8][8] = {};
    gemm_core<16, false>(g_att, w, ATTc, HIDc, ATTc, m0, n0, acc);

    const int ty = threadIdx.x >> 4, tx = threadIdx.x & 15;
    #pragma unroll
    for (int i = 0; i < 8; i++) {
        int m = m0 + ty * 8 + i;
        int nb = n0 + tx * 8;
        float4 o0 = make_float4(acc[i][0] + bias[nb + 0], acc[i][1] + bias[nb + 1],
                                acc[i][2] + bias[nb + 2], acc[i][3] + bias[nb + 3]);
        float4 o1 = make_float4(acc[i][4] + bias[nb + 4], acc[i][5] + bias[nb + 5],
                                acc[i][6] + bias[nb + 6], acc[i][7] + bias[nb + 7]);
        float* p = &out[(size_t)m * HIDc + nb];
        *reinterpret_cast<float4*>(p)     = o0;
        *reinterpret_cast<float4*>(p + 4) = o1;
    }
}

// ---------------------------------------------------------------------------
// Entry point. Inputs (metadata order): x, w_qkv, b_qkv, w_out, b_out.
// Output: fp32 [B, N, HID]. All launches are plain kernels -> graph-capturable.
// ---------------------------------------------------------------------------
extern "C" void kernel_launch(void* const* d_in, const int* in_sizes, int n_in,
                              void* d_out, int out_size)
{
    const float* x     = (const float*)d_in[0];
    const float* w_qkv = (const float*)d_in[1];
    const float* b_qkv = (const float*)d_in[2];
    const float* w_out = (const float*)d_in[3];
    const float* b_out = (const float*)d_in[4];
    float* out = (float*)d_out;

    qkv_kernel<<<dim3(27, 32), 256>>>(x, w_qkv, b_qkv);
    qk_kernel<<<dim3(8, 8, 64), 256>>>();
    softmax_kernel<<<65536, 256>>>();
    pv_kernel<<<dim3(8, 64), 256>>>();
    out_kernel<<<dim3(9, 32), 256>>>(w_out, b_out, out);
}